// round 1
// baseline (speedup 1.0000x reference)
#include <cuda_runtime.h>
#include <math.h>

#define N_NODES 4096
#define FIN     128
#define NHEAD   8
#define FOUT    64
#define HF      512                 // NHEAD*FOUT
#define OUT_ELEMS (N_NODES*HF)      // 2097152
#define ADJ_ELEMS (N_NODES*N_NODES) // 16777216
#define MAXDEG  512

// Scratch (allocation-free rule: __device__ globals)
__device__ float g_proj[N_NODES*HF];   // [n][h*64+d]
__device__ float g_skip[N_NODES*HF];
__device__ float g_ssrc[NHEAD*N_NODES];
__device__ float g_stgt[NHEAD*N_NODES];

// ---------------------------------------------------------------------------
// Kernel 1: fused projection GEMM.  C[4096,1024] = x[4096,128] @ [Wp;Ws]^T
// Block: 128 (rows) x 64 (cols), 256 threads, 8x4 micro-tile, K-tile 32.
// ---------------------------------------------------------------------------
__global__ __launch_bounds__(256) void gemm_kernel(
    const float* __restrict__ x,
    const float* __restrict__ Wp,
    const float* __restrict__ Ws)
{
    __shared__ float xs[32][129];   // [k][m], pad 1 -> conflict-free
    __shared__ float ws[32][65];    // [k][o]

    const int bm = blockIdx.y * 128;
    const int bo = blockIdx.x * 64;          // 0..960
    const int t  = threadIdx.x;
    const int tx = t & 15;                    // col group
    const int ty = t >> 4;                    // row group

    float acc[8][4];
#pragma unroll
    for (int i = 0; i < 8; i++)
#pragma unroll
        for (int j = 0; j < 4; j++) acc[i][j] = 0.f;

    const float* Wb = (bo < HF) ? (Wp + (size_t)bo * FIN)
                                : (Ws + (size_t)(bo - HF) * FIN);

    for (int kt = 0; kt < FIN; kt += 32) {
        // load x tile: 128 rows x 32 k = 1024 float4, 4 per thread (transpose)
#pragma unroll
        for (int v = 0; v < 4; v++) {
            int idx = t + v * 256;
            int row = idx >> 3, f4 = idx & 7;
            float4 xv = *reinterpret_cast<const float4*>(
                x + (size_t)(bm + row) * FIN + kt + f4 * 4);
            xs[f4*4+0][row] = xv.x; xs[f4*4+1][row] = xv.y;
            xs[f4*4+2][row] = xv.z; xs[f4*4+3][row] = xv.w;
        }
        // load W tile: 64 rows x 32 k = 512 float4, 2 per thread (transpose)
#pragma unroll
        for (int v = 0; v < 2; v++) {
            int idx = t + v * 256;
            int o = idx >> 3, f4 = idx & 7;
            float4 wv = *reinterpret_cast<const float4*>(
                Wb + (size_t)o * FIN + kt + f4 * 4);
            ws[f4*4+0][o] = wv.x; ws[f4*4+1][o] = wv.y;
            ws[f4*4+2][o] = wv.z; ws[f4*4+3][o] = wv.w;
        }
        __syncthreads();
#pragma unroll
        for (int k = 0; k < 32; k++) {
            float a[8], b[4];
#pragma unroll
            for (int i = 0; i < 8; i++) a[i] = xs[k][ty*8 + i];
#pragma unroll
            for (int j = 0; j < 4; j++) b[j] = ws[k][tx*4 + j];
#pragma unroll
            for (int i = 0; i < 8; i++)
#pragma unroll
                for (int j = 0; j < 4; j++) acc[i][j] += a[i] * b[j];
        }
        __syncthreads();
    }

#pragma unroll
    for (int i = 0; i < 8; i++) {
        int m = bm + ty*8 + i;
#pragma unroll
        for (int j = 0; j < 4; j++) {
            int o = bo + tx*4 + j;
            if (o < HF) g_proj[(size_t)m*HF + o]        = acc[i][j];
            else        g_skip[(size_t)m*HF + (o - HF)] = acc[i][j];
        }
    }
}

// ---------------------------------------------------------------------------
// Kernel 2: per-node attention scores  s_src[h][n], s_tgt[h][n]
// One warp per node; 8 heads, 64-dim dot each.
// ---------------------------------------------------------------------------
__global__ __launch_bounds__(256) void score_kernel(
    const float* __restrict__ a_src,
    const float* __restrict__ a_tgt)
{
    int gw   = (blockIdx.x * 256 + threadIdx.x) >> 5;
    int lane = threadIdx.x & 31;
    if (gw >= N_NODES) return;
    const float* pr = g_proj + (size_t)gw * HF;
#pragma unroll
    for (int h = 0; h < NHEAD; h++) {
        float p0 = pr[h*64 + lane];
        float p1 = pr[h*64 + 32 + lane];
        float ss = p0 * a_src[h*64 + lane] + p1 * a_src[h*64 + 32 + lane];
        float st = p0 * a_tgt[h*64 + lane] + p1 * a_tgt[h*64 + 32 + lane];
#pragma unroll
        for (int off = 16; off; off >>= 1) {
            ss += __shfl_xor_sync(0xffffffffu, ss, off);
            st += __shfl_xor_sync(0xffffffffu, st, off);
        }
        if (lane == 0) {
            g_ssrc[h*N_NODES + gw] = ss;
            g_stgt[h*N_NODES + gw] = st;
        }
    }
}

// ---------------------------------------------------------------------------
// Kernel 3: sparse attention. One block per row i.
// Phase 1: scan adj row, deterministic compaction of neighbor list
//          (also streams adj to output tuple slot).
// Phase 2: per-head masked softmax (max/exp/sum) over neighbors.
// Phase 3: gather-accumulate proj rows (one 2KB row serves all 8 heads),
//          add skip + bias, ELU, store.
// ---------------------------------------------------------------------------
__global__ __launch_bounds__(256) void attn_kernel(
    const float* __restrict__ adj,
    const float* __restrict__ bias,
    float* __restrict__ out,
    float* __restrict__ out_adj,
    int write_adj)
{
    __shared__ int   nbr[MAXDEG];
    __shared__ float wsm[NHEAD * MAXDEG];
    __shared__ int   warpsum[8];
    __shared__ float redf[8];
    __shared__ float ssum[NHEAD];

    const int i    = blockIdx.x;
    const int t    = threadIdx.x;
    const int lane = t & 31;
    const int w    = t >> 5;

    const float4* arow = reinterpret_cast<const float4*>(adj + (size_t)i * N_NODES);
    float4*       orow = reinterpret_cast<float4*>(out_adj + (size_t)i * N_NODES);

    // ---- Phase 1: ordered neighbor compaction -----------------------------
    int cnt = 0;
#pragma unroll
    for (int it = 0; it < 4; it++) {
        int idx4 = it * 256 + t;
        float4 a = arow[idx4];
        if (write_adj) orow[idx4] = a;
        int p0 = a.x > -0.5f;
        int p1 = a.y > -0.5f;
        int p2 = a.z > -0.5f;
        int p3 = a.w > -0.5f;
        int c = p0 + p1 + p2 + p3;
        int v = c;
#pragma unroll
        for (int off = 1; off < 32; off <<= 1) {
            int n = __shfl_up_sync(0xffffffffu, v, off);
            if (lane >= off) v += n;
        }
        if (lane == 31) warpsum[w] = v;
        __syncthreads();
        int wbase = 0, tot = 0;
#pragma unroll
        for (int ww = 0; ww < 8; ww++) {
            int s = warpsum[ww];
            if (ww < w) wbase += s;
            tot += s;
        }
        int pos = cnt + wbase + (v - c);   // exclusive prefix, j-ordered
        int j = idx4 * 4;
        if (p0 && pos < MAXDEG) nbr[pos++] = j;
        if (p1 && pos < MAXDEG) nbr[pos++] = j + 1;
        if (p2 && pos < MAXDEG) nbr[pos++] = j + 2;
        if (p3 && pos < MAXDEG) nbr[pos++] = j + 3;
        cnt += tot;
        __syncthreads();
    }
    const int deg = min(cnt, MAXDEG);

    // ---- Phase 2: per-head softmax over neighbors -------------------------
    for (int h = 0; h < NHEAD; h++) {
        float ssrc = g_ssrc[h*N_NODES + i];
        float* wrow = wsm + h * MAXDEG;
        float lmax = -1e30f;
        for (int k = t; k < deg; k += 256) {
            float xv = ssrc + g_stgt[h*N_NODES + nbr[k]];
            float l  = xv >= 0.f ? xv : 0.2f * xv;    // leaky_relu(0.2)
            wrow[k] = l;
            lmax = fmaxf(lmax, l);
        }
#pragma unroll
        for (int off = 16; off; off >>= 1)
            lmax = fmaxf(lmax, __shfl_xor_sync(0xffffffffu, lmax, off));
        if (lane == 0) redf[w] = lmax;
        __syncthreads();
        float m = redf[0];
#pragma unroll
        for (int ww = 1; ww < 8; ww++) m = fmaxf(m, redf[ww]);
        __syncthreads();                 // redf reuse below
        float lsum = 0.f;
        for (int k = t; k < deg; k += 256) {
            float e = expf(wrow[k] - m);
            wrow[k] = e;
            lsum += e;
        }
#pragma unroll
        for (int off = 16; off; off >>= 1)
            lsum += __shfl_xor_sync(0xffffffffu, lsum, off);
        if (lane == 0) redf[w] = lsum;
        __syncthreads();
        if (t == 0) {
            float s = 0.f;
#pragma unroll
            for (int ww = 0; ww < 8; ww++) s += redf[ww];
            ssum[h] = s;
        }
        __syncthreads();
    }

    // ---- Phase 3: gather-accumulate (all heads share each proj row) -------
    const int p1 = t, p2 = t + 256;
    const float* w1 = wsm + (p1 >> 6) * MAXDEG;
    const float* w2 = wsm + (p2 >> 6) * MAXDEG;
    float acc1 = 0.f, acc2 = 0.f;
    int k = 0;
    for (; k + 4 <= deg; k += 4) {
        int n0 = nbr[k], n1 = nbr[k+1], n2 = nbr[k+2], n3 = nbr[k+3];
        const float* r0 = g_proj + (size_t)n0 * HF;
        const float* r1 = g_proj + (size_t)n1 * HF;
        const float* r2 = g_proj + (size_t)n2 * HF;
        const float* r3 = g_proj + (size_t)n3 * HF;
        float a0 = r0[p1], a1 = r1[p1], a2 = r2[p1], a3 = r3[p1];
        float b0 = r0[p2], b1 = r1[p2], b2 = r2[p2], b3 = r3[p2];
        acc1 += w1[k]   * a0;
        acc1 += w1[k+1] * a1;
        acc1 += w1[k+2] * a2;
        acc1 += w1[k+3] * a3;
        acc2 += w2[k]   * b0;
        acc2 += w2[k+1] * b1;
        acc2 += w2[k+2] * b2;
        acc2 += w2[k+3] * b3;
    }
    for (; k < deg; k++) {
        const float* r = g_proj + (size_t)nbr[k] * HF;
        acc1 += w1[k] * r[p1];
        acc2 += w2[k] * r[p2];
    }

    float v1 = acc1 / ssum[p1 >> 6] + g_skip[(size_t)i*HF + p1] + bias[p1];
    float v2 = acc2 / ssum[p2 >> 6] + g_skip[(size_t)i*HF + p2] + bias[p2];
    out[(size_t)i*HF + p1] = v1 > 0.f ? v1 : expm1f(v1);   // ELU(alpha=1)
    out[(size_t)i*HF + p2] = v2 > 0.f ? v2 : expm1f(v2);
}

// ---------------------------------------------------------------------------
extern "C" void kernel_launch(void* const* d_in, const int* in_sizes, int n_in,
                              void* d_out, int out_size)
{
    const float* x     = (const float*)d_in[0];
    const float* adj   = (const float*)d_in[1];
    const float* Wp    = (const float*)d_in[2];
    const float* a_src = (const float*)d_in[3];
    const float* a_tgt = (const float*)d_in[4];
    const float* Ws    = (const float*)d_in[5];
    const float* bias  = (const float*)d_in[6];
    float* out = (float*)d_out;

    // Tuple output (out, adj): copy adj into the tail slot if present.
    int write_adj = (out_size >= OUT_ELEMS + ADJ_ELEMS) ? 1 : 0;
    float* out_adj = write_adj ? (out + OUT_ELEMS) : out;

    dim3 ggrid(1024 / 64, N_NODES / 128);          // (16, 32)
    gemm_kernel<<<ggrid, 256>>>(x, Wp, Ws);
    score_kernel<<<N_NODES / 8, 256>>>(a_src, a_tgt);
    attn_kernel<<<N_NODES, 256>>>(adj, bias, out, out_adj, write_adj);
}

// round 2
// speedup vs baseline: 1.2011x; 1.2011x over previous
#include <cuda_runtime.h>
#include <math.h>

#define N_NODES 4096
#define FIN     128
#define NHEAD   8
#define FOUT    64
#define HF      512                 // NHEAD*FOUT
#define OUT_ELEMS (N_NODES*HF)      // 2097152
#define ADJ_ELEMS (N_NODES*N_NODES) // 16777216
#define MAXDEG  512

// Scratch (allocation-free rule: __device__ globals)
__device__ float g_proj[N_NODES*HF];   // [n][h*64+d]
__device__ float g_skip[N_NODES*HF];
__device__ float g_ssrc[NHEAD*N_NODES];
__device__ float g_stgt[NHEAD*N_NODES];

// ---------------------------------------------------------------------------
// Kernel 1: fused projection GEMM.  C[4096,1024] = x[4096,128] @ [Wp;Ws]^T
// 128x128 block tile, BK=16, 256 threads, 8x8 micro-tile (1.0 FMA/byte of LDS).
// ---------------------------------------------------------------------------
#define BM 128
#define BN 128
#define BK 16

__global__ __launch_bounds__(256, 2) void gemm_kernel(
    const float* __restrict__ x,
    const float* __restrict__ Wp,
    const float* __restrict__ Ws)
{
    __shared__ float xs[BK][BM + 4];   // stride 132 floats: 16B-aligned rows, 4-bank skew
    __shared__ float ws[BK][BN + 4];

    const int bm = blockIdx.y * BM;
    const int bo = blockIdx.x * BN;          // 0,128,...,896 — each tile fully in Wp or Ws
    const int t  = threadIdx.x;
    const int tx = t & 15;                    // col group (8 cols each)
    const int ty = t >> 4;                    // row group (8 rows each)

    float acc[8][8];
#pragma unroll
    for (int i = 0; i < 8; i++)
#pragma unroll
        for (int j = 0; j < 8; j++) acc[i][j] = 0.f;

    const float* Wb = (bo < HF) ? (Wp + (size_t)bo * FIN)
                                : (Ws + (size_t)(bo - HF) * FIN);

    for (int kt = 0; kt < FIN; kt += BK) {
        // x tile: 128 rows x 16 k = 512 float4 -> 2 per thread (transpose into [k][m])
#pragma unroll
        for (int v = 0; v < 2; v++) {
            int idx = t + v * 256;
            int row = idx >> 2, f4 = idx & 3;
            float4 xv = *reinterpret_cast<const float4*>(
                x + (size_t)(bm + row) * FIN + kt + f4 * 4);
            xs[f4*4+0][row] = xv.x; xs[f4*4+1][row] = xv.y;
            xs[f4*4+2][row] = xv.z; xs[f4*4+3][row] = xv.w;
        }
        // W tile: 128 out x 16 k = 512 float4 -> 2 per thread (transpose into [k][o])
#pragma unroll
        for (int v = 0; v < 2; v++) {
            int idx = t + v * 256;
            int o = idx >> 2, f4 = idx & 3;
            float4 wv = *reinterpret_cast<const float4*>(
                Wb + (size_t)o * FIN + kt + f4 * 4);
            ws[f4*4+0][o] = wv.x; ws[f4*4+1][o] = wv.y;
            ws[f4*4+2][o] = wv.z; ws[f4*4+3][o] = wv.w;
        }
        __syncthreads();
#pragma unroll
        for (int k = 0; k < BK; k++) {
            float a[8], b[8];
            *reinterpret_cast<float4*>(a)     = *reinterpret_cast<const float4*>(&xs[k][ty*8]);
            *reinterpret_cast<float4*>(a + 4) = *reinterpret_cast<const float4*>(&xs[k][ty*8+4]);
            *reinterpret_cast<float4*>(b)     = *reinterpret_cast<const float4*>(&ws[k][tx*8]);
            *reinterpret_cast<float4*>(b + 4) = *reinterpret_cast<const float4*>(&ws[k][tx*8+4]);
#pragma unroll
            for (int i = 0; i < 8; i++)
#pragma unroll
                for (int j = 0; j < 8; j++) acc[i][j] = fmaf(a[i], b[j], acc[i][j]);
        }
        __syncthreads();
    }

    float* dst = (bo < HF) ? g_proj : g_skip;
    const int cb = (bo < HF) ? bo : (bo - HF);
#pragma unroll
    for (int i = 0; i < 8; i++) {
        int m = bm + ty*8 + i;
        float* drow = dst + (size_t)m * HF + cb + tx*8;
        float4 v0 = make_float4(acc[i][0], acc[i][1], acc[i][2], acc[i][3]);
        float4 v1 = make_float4(acc[i][4], acc[i][5], acc[i][6], acc[i][7]);
        *reinterpret_cast<float4*>(drow)     = v0;
        *reinterpret_cast<float4*>(drow + 4) = v1;
    }
}

// ---------------------------------------------------------------------------
// Kernel 2: per-node attention scores  s_src[h][n], s_tgt[h][n]
// One warp per node; 8 heads, 64-dim dot each.
// ---------------------------------------------------------------------------
__global__ __launch_bounds__(256) void score_kernel(
    const float* __restrict__ a_src,
    const float* __restrict__ a_tgt)
{
    int gw   = (blockIdx.x * 256 + threadIdx.x) >> 5;
    int lane = threadIdx.x & 31;
    if (gw >= N_NODES) return;
    const float* pr = g_proj + (size_t)gw * HF;
#pragma unroll
    for (int h = 0; h < NHEAD; h++) {
        float p0 = pr[h*64 + lane];
        float p1 = pr[h*64 + 32 + lane];
        float ss = p0 * a_src[h*64 + lane] + p1 * a_src[h*64 + 32 + lane];
        float st = p0 * a_tgt[h*64 + lane] + p1 * a_tgt[h*64 + 32 + lane];
#pragma unroll
        for (int off = 16; off; off >>= 1) {
            ss += __shfl_xor_sync(0xffffffffu, ss, off);
            st += __shfl_xor_sync(0xffffffffu, st, off);
        }
        if (lane == 0) {
            g_ssrc[h*N_NODES + gw] = ss;
            g_stgt[h*N_NODES + gw] = st;
        }
    }
}

// ---------------------------------------------------------------------------
// Kernel 3: sparse attention. One block per row i.
// Phase 1: scan adj row, deterministic compaction of neighbor list
//          (also streams adj to output tuple slot).
// Phase 2: per-head masked softmax — WARP-PER-HEAD (warp w owns head w),
//          warp-local reductions, only one block barrier at the end.
// Phase 3: gather-accumulate proj rows (one 2KB row serves all 8 heads),
//          add skip + bias, ELU, store.
// ---------------------------------------------------------------------------
__global__ __launch_bounds__(256) void attn_kernel(
    const float* __restrict__ adj,
    const float* __restrict__ bias,
    float* __restrict__ out,
    float* __restrict__ out_adj,
    int write_adj)
{
    __shared__ int   nbr[MAXDEG];
    __shared__ float wsm[NHEAD * MAXDEG];
    __shared__ int   warpsum[8];
    __shared__ float ssum[NHEAD];

    const int i    = blockIdx.x;
    const int t    = threadIdx.x;
    const int lane = t & 31;
    const int w    = t >> 5;

    const float4* arow = reinterpret_cast<const float4*>(adj + (size_t)i * N_NODES);
    float4*       orow = reinterpret_cast<float4*>(out_adj + (size_t)i * N_NODES);

    // ---- Phase 1: ordered neighbor compaction -----------------------------
    int cnt = 0;
#pragma unroll
    for (int it = 0; it < 4; it++) {
        int idx4 = it * 256 + t;
        float4 a = arow[idx4];
        if (write_adj) orow[idx4] = a;
        int p0 = a.x > -0.5f;
        int p1 = a.y > -0.5f;
        int p2 = a.z > -0.5f;
        int p3 = a.w > -0.5f;
        int c = p0 + p1 + p2 + p3;
        int v = c;
#pragma unroll
        for (int off = 1; off < 32; off <<= 1) {
            int n = __shfl_up_sync(0xffffffffu, v, off);
            if (lane >= off) v += n;
        }
        if (lane == 31) warpsum[w] = v;
        __syncthreads();
        int wbase = 0, tot = 0;
#pragma unroll
        for (int ww = 0; ww < 8; ww++) {
            int s = warpsum[ww];
            if (ww < w) wbase += s;
            tot += s;
        }
        int pos = cnt + wbase + (v - c);   // exclusive prefix, j-ordered
        int j = idx4 * 4;
        if (p0 && pos < MAXDEG) nbr[pos++] = j;
        if (p1 && pos < MAXDEG) nbr[pos++] = j + 1;
        if (p2 && pos < MAXDEG) nbr[pos++] = j + 2;
        if (p3 && pos < MAXDEG) nbr[pos++] = j + 3;
        cnt += tot;
        __syncthreads();
    }
    const int deg = min(cnt, MAXDEG);

    // ---- Phase 2: warp-per-head softmax over neighbors --------------------
    {
        const int h = w;                       // warp w owns head h
        const float ssrc = g_ssrc[h*N_NODES + i];
        const float* stgt = g_stgt + h*N_NODES;
        float* wrow = wsm + h * MAXDEG;

        float lmax = -1e30f;
        for (int k = lane; k < deg; k += 32) {
            float xv = ssrc + stgt[nbr[k]];
            float l  = xv >= 0.f ? xv : 0.2f * xv;    // leaky_relu(0.2)
            wrow[k] = l;
            lmax = fmaxf(lmax, l);
        }
#pragma unroll
        for (int off = 16; off; off >>= 1)
            lmax = fmaxf(lmax, __shfl_xor_sync(0xffffffffu, lmax, off));

        float lsum = 0.f;
        for (int k = lane; k < deg; k += 32) {
            float e = expf(wrow[k] - lmax);
            wrow[k] = e;
            lsum += e;
        }
#pragma unroll
        for (int off = 16; off; off >>= 1)
            lsum += __shfl_xor_sync(0xffffffffu, lsum, off);
        if (lane == 0) ssum[h] = lsum;
    }
    __syncthreads();

    // ---- Phase 3: gather-accumulate (all heads share each proj row) -------
    const int p1 = t, p2 = t + 256;
    const float* w1 = wsm + (p1 >> 6) * MAXDEG;
    const float* w2 = wsm + (p2 >> 6) * MAXDEG;
    float acc1 = 0.f, acc2 = 0.f;
    int k = 0;
    for (; k + 4 <= deg; k += 4) {
        int n0 = nbr[k], n1 = nbr[k+1], n2 = nbr[k+2], n3 = nbr[k+3];
        const float* r0 = g_proj + (size_t)n0 * HF;
        const float* r1 = g_proj + (size_t)n1 * HF;
        const float* r2 = g_proj + (size_t)n2 * HF;
        const float* r3 = g_proj + (size_t)n3 * HF;
        float a0 = r0[p1], a1 = r1[p1], a2 = r2[p1], a3 = r3[p1];
        float b0 = r0[p2], b1 = r1[p2], b2 = r2[p2], b3 = r3[p2];
        acc1 += w1[k]   * a0;
        acc1 += w1[k+1] * a1;
        acc1 += w1[k+2] * a2;
        acc1 += w1[k+3] * a3;
        acc2 += w2[k]   * b0;
        acc2 += w2[k+1] * b1;
        acc2 += w2[k+2] * b2;
        acc2 += w2[k+3] * b3;
    }
    for (; k < deg; k++) {
        const float* r = g_proj + (size_t)nbr[k] * HF;
        acc1 += w1[k] * r[p1];
        acc2 += w2[k] * r[p2];
    }

    float v1 = acc1 / ssum[p1 >> 6] + g_skip[(size_t)i*HF + p1] + bias[p1];
    float v2 = acc2 / ssum[p2 >> 6] + g_skip[(size_t)i*HF + p2] + bias[p2];
    out[(size_t)i*HF + p1] = v1 > 0.f ? v1 : expm1f(v1);   // ELU(alpha=1)
    out[(size_t)i*HF + p2] = v2 > 0.f ? v2 : expm1f(v2);
}

// ---------------------------------------------------------------------------
extern "C" void kernel_launch(void* const* d_in, const int* in_sizes, int n_in,
                              void* d_out, int out_size)
{
    const float* x     = (const float*)d_in[0];
    const float* adj   = (const float*)d_in[1];
    const float* Wp    = (const float*)d_in[2];
    const float* a_src = (const float*)d_in[3];
    const float* a_tgt = (const float*)d_in[4];
    const float* Ws    = (const float*)d_in[5];
    const float* bias  = (const float*)d_in[6];
    float* out = (float*)d_out;

    // Tuple output (out, adj): copy adj into the tail slot if present.
    int write_adj = (out_size >= OUT_ELEMS + ADJ_ELEMS) ? 1 : 0;
    float* out_adj = write_adj ? (out + OUT_ELEMS) : out;

    dim3 ggrid(1024 / BN, N_NODES / BM);          // (8, 32)
    gemm_kernel<<<ggrid, 256>>>(x, Wp, Ws);
    score_kernel<<<N_NODES / 8, 256>>>(a_src, a_tgt);
    attn_kernel<<<N_NODES, 256>>>(adj, bias, out, out_adj, write_adj);
}